// round 13
// baseline (speedup 1.0000x reference)
#include <cuda_runtime.h>
#include <math.h>

#define NROWS 6144
#define KDIM  128
#define NCLS  200
#define RPB   2
#define NBLK  (NROWS / RPB)      // 3072
#define NTHR  512
#define NWARP (NTHR / 32)        // 16
#define SIMCAP 128
#define QBLKS 192

// symmetric GEMM tiling (K staged in two halves -> 64 KB smem, 2 CTAs/SM)
#define GTT 128
#define GKH 64
#define GTHR2 256
#define GSMEM2 (GKH * GTT * 8)   // 65536

// ---- stats kernel shared memory layout (byte offsets) ----
#define SM_ROWS   0                      // [2][6144] f32 = 49152
#define SM_SIMM   49152                  // packed 4 j/byte (2 bits/j) = 1536
#define SM_HIST   50688                  // [2][256] int = 2048
#define SM_VHIST  52736                  // [2][256] f32 = 2048 (simv aliased pre-refine)
#define SM_SIMV   SM_VHIST               // [2][128] f32 = 1024 (alias)
#define SM_SCNT   54784                  // 32
#define SM_MISC   54816                  // 384
#define SM_WSCR   55200                  // 128
#define SMEM_BYTES 55328

#define MISC_SUMS  (SM_MISC + 0)
#define MISC_SGT   (SM_MISC + 16)
#define MISC_VSUF  (SM_MISC + 32)
#define MISC_SMIN  (SM_MISC + 48)
#define MISC_BP    (SM_MISC + 64)
#define MISC_BPD   (SM_MISC + 80)
#define MISC_LP    (SM_MISC + 96)
#define MISC_LN    (SM_MISC + 112)
#define MISC_NSIM  (SM_MISC + 128)
#define MISC_KSEL  (SM_MISC + 144)
#define MISC_KK    (SM_MISC + 160)
#define MISC_PFX   (SM_MISC + 176)
#define MISC_EP    (SM_MISC + 192)
#define MISC_EN    (SM_MISC + 208)

static __device__ float g_uhT[KDIM * NROWS];            // transposed tanh(u): [k][j]
static __device__ float g_inner[(size_t)NROWS * NROWS]; // full inner-product matrix
static __device__ float g_colsum[KDIM];                 // sum over j of uhT[k][j]
static __device__ float g_rowsum[NROWS];                // uh_i . colsum
static __device__ int   g_label[NROWS];
static __device__ float g_rowpos[NROWS];
static __device__ float g_rowneg[NROWS];
static __device__ int   g_valid[NROWS];
static __device__ float g_qpart[QBLKS];

__device__ __forceinline__ unsigned f2key(float f) {
    unsigned u = __float_as_uint(f);
    return u ^ ((unsigned)(((int)u) >> 31) | 0x80000000u);
}
__device__ __forceinline__ float clip64(float x) { return fminf(fmaxf(x, 0.f), 64.f); }
__device__ __forceinline__ float softplus_f(float x) {
    return fmaxf(x, 0.f) + __logf(1.f + __expf(-fabsf(x)));
}
__device__ __forceinline__ unsigned long long packww(float w) {
    unsigned long long r;
    asm("mov.b64 %0, {%1, %1};" : "=l"(r) : "f"(w));
    return r;
}
__device__ __forceinline__ unsigned s2u(const void* p) {
    unsigned a;
    asm("{ .reg .u64 t; cvta.to.shared.u64 t, %1; cvt.u32.u64 %0, t; }"
        : "=r"(a) : "l"(p));
    return a;
}
__device__ __forceinline__ void cpasync16(unsigned saddr, const void* g) {
    asm volatile("cp.async.cg.shared.global [%0], [%1], 16;" :: "r"(saddr), "l"(g));
}
__device__ __forceinline__ float u64lo(unsigned long long a) {
    return __uint_as_float((unsigned)(a & 0xFFFFFFFFull));
}
__device__ __forceinline__ float u64hi(unsigned long long a) {
    return __uint_as_float((unsigned)(a >> 32));
}
__device__ __forceinline__ void aggHistAdd(int* hist, int idx) {
    unsigned active = __activemask();
    unsigned mask = __match_any_sync(active, idx);
    int leader = __ffs(mask) - 1;
    if ((int)(threadIdx.x & 31) == leader)
        atomicAdd(hist + idx, __popc(mask));
}

// deterministic 2-value block reductions (fixed order)
__device__ __forceinline__ void blockSum2F(float v[2], float* wscr, float* out2, int tid) {
    int lane = tid & 31, wid = tid >> 5;
    #pragma unroll
    for (int r = 0; r < 2; r++) {
        #pragma unroll
        for (int o = 16; o > 0; o >>= 1) v[r] += __shfl_xor_sync(0xFFFFFFFFu, v[r], o);
    }
    if (lane == 0) {
        wscr[wid * 2] = v[0];
        wscr[wid * 2 + 1] = v[1];
    }
    __syncthreads();
    if (tid < 2) {
        float s = 0.f;
        #pragma unroll
        for (int w = 0; w < NWARP; w++) s += wscr[w * 2 + tid];
        out2[tid] = s;
    }
    __syncthreads();
}
__device__ __forceinline__ void blockSum2I(int v[2], int* wscr, int* out2, int tid) {
    int lane = tid & 31, wid = tid >> 5;
    #pragma unroll
    for (int r = 0; r < 2; r++) {
        #pragma unroll
        for (int o = 16; o > 0; o >>= 1) v[r] += __shfl_xor_sync(0xFFFFFFFFu, v[r], o);
    }
    if (lane == 0) {
        wscr[wid * 2] = v[0];
        wscr[wid * 2 + 1] = v[1];
    }
    __syncthreads();
    if (tid < 2) {
        int s = 0;
        #pragma unroll
        for (int w = 0; w < NWARP; w++) s += wscr[w * 2 + tid];
        out2[tid] = s;
    }
    __syncthreads();
}

__device__ __forceinline__ int radixPick(const int* histrow, int kk, int lane,
                                         int* kknext_out) {
    int topbin = 255 - lane * 8;
    int csum = 0;
    #pragma unroll
    for (int b = 0; b < 8; b++) csum += histrow[topbin - b];
    int incl = csum;
    #pragma unroll
    for (int o = 1; o < 32; o <<= 1) {
        int t = __shfl_up_sync(0xFFFFFFFFu, incl, o);
        if (lane >= o) incl += t;
    }
    int excl = incl - csum;
    int hit = (excl < kk && kk <= incl) ? 1 : 0;
    unsigned who = __ballot_sync(0xFFFFFFFFu, hit);
    int src = __ffs(who) - 1;
    int bfound = 0, kknext = 0;
    if (hit) {
        int running = excl;
        #pragma unroll
        for (int b = 0; b < 8; b++) {
            int bin = topbin - b;
            int c = histrow[bin];
            running += c;
            if (running >= kk) { bfound = bin; kknext = kk - (running - c); break; }
        }
    }
    bfound = __shfl_sync(0xFFFFFFFFu, bfound, src);
    kknext = __shfl_sync(0xFFFFFFFFu, kknext, src);
    *kknext_out = kknext;
    return bfound;
}

// ---------------- kernel 0: tanh + quantization partials + transpose ----------
__global__ void __launch_bounds__(256) tanh_kernel(const float* __restrict__ u) {
    __shared__ float tile[32][129];
    __shared__ float scr[8];
    const int tid = threadIdx.x;
    const int i0 = blockIdx.x * 32;
    float q = 0.f;
    for (int idx = tid; idx < 32 * KDIM; idx += 256) {
        int r = idx >> 7, k = idx & 127;
        float x = tanhf(u[(i0 + r) * KDIM + k]);
        tile[r][k] = x;
        float s = (x > 0.f) ? 1.f : ((x < 0.f) ? -1.f : 0.f);
        float d = x - s;
        q += d * d;
    }
    __syncthreads();
    for (int idx = tid; idx < 32 * KDIM; idx += 256) {
        int k = idx >> 5, i = idx & 31;
        g_uhT[k * NROWS + i0 + i] = tile[i][k];
    }
    #pragma unroll
    for (int o = 16; o > 0; o >>= 1) q += __shfl_xor_sync(0xFFFFFFFFu, q, o);
    if ((tid & 31) == 0) scr[tid >> 5] = q;
    __syncthreads();
    if (tid == 0) {
        float s = 0.f;
        for (int w = 0; w < 8; w++) s += scr[w];
        g_qpart[blockIdx.x] = s;
    }
}

// ---------------- kernel 1: one-hot -> label (warp per row) ------------------
__global__ void __launch_bounds__(256) label_kernel(const int* __restrict__ y) {
    int w = (blockIdx.x * blockDim.x + threadIdx.x) >> 5;
    int lane = threadIdx.x & 31;
    if (w < NROWS) {
        const int* yr = y + (size_t)w * NCLS;
        int lab = 0;
        for (int c = lane; c < NCLS; c += 32)
            if (yr[c] != 0) lab = c;
        #pragma unroll
        for (int o = 16; o > 0; o >>= 1)
            lab = max(lab, __shfl_xor_sync(0xFFFFFFFFu, lab, o));
        if (lane == 0) g_label[w] = lab;
    }
}

// ---------------- kernel 1b: colsum[k] = sum_j uhT[k][j] ---------------------
__global__ void __launch_bounds__(256) colsum_kernel() {
    __shared__ float scr[8];
    const int k = blockIdx.x;
    const int tid = threadIdx.x;
    const float4* p = (const float4*)(g_uhT + (size_t)k * NROWS);
    float a = 0.f;
    for (int t = tid; t < NROWS / 4; t += 256) {
        float4 v = p[t];
        a += (v.x + v.y) + (v.z + v.w);
    }
    #pragma unroll
    for (int o = 16; o > 0; o >>= 1) a += __shfl_xor_sync(0xFFFFFFFFu, a, o);
    if ((tid & 31) == 0) scr[tid >> 5] = a;
    __syncthreads();
    if (tid == 0) {
        float s = 0.f;
        for (int w = 0; w < 8; w++) s += scr[w];
        g_colsum[k] = s;
    }
}

// ---------------- kernel 1c: rowsum[i] = uh_i . colsum -----------------------
__global__ void __launch_bounds__(128) rowsum_kernel() {
    __shared__ float cs[KDIM];
    const int tid = threadIdx.x;
    if (tid < KDIM) cs[tid] = g_colsum[tid];
    __syncthreads();
    int i = blockIdx.x * 128 + tid;
    float a0 = 0.f, a1 = 0.f, a2 = 0.f, a3 = 0.f;
    #pragma unroll
    for (int k = 0; k < KDIM; k += 4) {
        a0 += g_uhT[(size_t)k * NROWS + i] * cs[k];
        a1 += g_uhT[(size_t)(k + 1) * NROWS + i] * cs[k + 1];
        a2 += g_uhT[(size_t)(k + 2) * NROWS + i] * cs[k + 2];
        a3 += g_uhT[(size_t)(k + 3) * NROWS + i] * cs[k + 3];
    }
    g_rowsum[i] = (a0 + a1) + (a2 + a3);
}

// ---------------- kernel 2: SYMMETRIC GEMM inner = uh @ uh^T -----------------
// 128x128 upper-triangle tiles; A staged in two K-halves (64 KB smem) so two
// CTAs co-reside per SM and hide each other's staging + memory latency.
__global__ void __launch_bounds__(GTHR2, 2) gemm_sym_kernel() {
    extern __shared__ unsigned long long apk[];   // [GKH][GTT] (a,a)-packed
    const int it = blockIdx.x, jt = blockIdx.y;
    if (jt < it) return;
    const int tid = threadIdx.x;
    const int i0 = it * GTT;
    const int j0 = jt * GTT;

    const int tii = (tid >> 4) * 8;
    const int tjj = (tid & 15) * 8;
    const float* Bp = g_uhT + (size_t)j0 + tjj;

    unsigned long long acc[8][4];
    #pragma unroll
    for (int i = 0; i < 8; i++)
        #pragma unroll
        for (int c = 0; c < 4; c++) acc[i][c] = 0ull;

    #pragma unroll
    for (int half = 0; half < 2; half++) {
        // stage this K-half of A (packed (a,a))
        if (half) __syncthreads();
        for (int t = tid; t < GKH * GTT; t += GTHR2) {
            int kk = t >> 7, i = t & 127;
            apk[kk * GTT + i] =
                packww(g_uhT[(size_t)(half * GKH + kk) * NROWS + i0 + i]);
        }
        __syncthreads();

        const float* Bh = Bp + (size_t)half * GKH * NROWS;
        ulonglong2 b01[2], b23[2];
        b01[0] = *(const ulonglong2*)(Bh);
        b23[0] = *(const ulonglong2*)(Bh + 4);
        b01[1] = *(const ulonglong2*)(Bh + (size_t)NROWS);
        b23[1] = *(const ulonglong2*)(Bh + (size_t)NROWS + 4);

        #pragma unroll 2
        for (int kk = 0; kk < GKH; kk++) {
            const int p = kk & 1;
            ulonglong2 cb01 = b01[p], cb23 = b23[p];
            if (kk + 2 < GKH) {
                b01[p] = *(const ulonglong2*)(Bh + (size_t)(kk + 2) * NROWS);
                b23[p] = *(const ulonglong2*)(Bh + (size_t)(kk + 2) * NROWS + 4);
            } else if (half == 0) {
                // prefetch start of next half
                const float* Bn = Bp + (size_t)GKH * NROWS;
                b01[p] = *(const ulonglong2*)(Bn + (size_t)(kk + 2 - GKH) * NROWS);
                b23[p] = *(const ulonglong2*)(Bn + (size_t)(kk + 2 - GKH) * NROWS + 4);
            }
            const ulonglong2* ap2 = (const ulonglong2*)(apk + kk * GTT + tii);
            ulonglong2 ap[4];
            ap[0] = ap2[0]; ap[1] = ap2[1]; ap[2] = ap2[2]; ap[3] = ap2[3];
            unsigned long long a[8];
            #pragma unroll
            for (int h = 0; h < 4; h++) { a[2 * h] = ap[h].x; a[2 * h + 1] = ap[h].y; }
            #pragma unroll
            for (int i = 0; i < 8; i++) {
                asm("fma.rn.f32x2 %0, %1, %2, %0;" : "+l"(acc[i][0]) : "l"(cb01.x), "l"(a[i]));
                asm("fma.rn.f32x2 %0, %1, %2, %0;" : "+l"(acc[i][1]) : "l"(cb01.y), "l"(a[i]));
                asm("fma.rn.f32x2 %0, %1, %2, %0;" : "+l"(acc[i][2]) : "l"(cb23.x), "l"(a[i]));
                asm("fma.rn.f32x2 %0, %1, %2, %0;" : "+l"(acc[i][3]) : "l"(cb23.y), "l"(a[i]));
            }
        }
    }

    #pragma unroll
    for (int i = 0; i < 8; i++) {
        size_t base = (size_t)(i0 + tii + i) * NROWS + j0 + tjj;
        float4 v1, v2;
        v1.x = u64lo(acc[i][0]); v1.y = u64hi(acc[i][0]);
        v1.z = u64lo(acc[i][1]); v1.w = u64hi(acc[i][1]);
        v2.x = u64lo(acc[i][2]); v2.y = u64hi(acc[i][2]);
        v2.z = u64lo(acc[i][3]); v2.w = u64hi(acc[i][3]);
        __stcs((float4*)(g_inner + base), v1);
        __stcs((float4*)(g_inner + base + 4), v2);
    }

    if (it != jt) {
        #pragma unroll
        for (int c = 0; c < 8; c++) {
            float col[8];
            #pragma unroll
            for (int i = 0; i < 8; i++)
                col[i] = (c & 1) ? u64hi(acc[i][c >> 1]) : u64lo(acc[i][c >> 1]);
            size_t base = (size_t)(j0 + tjj + c) * NROWS + i0 + tii;
            float4 v1, v2;
            v1.x = col[0]; v1.y = col[1]; v1.z = col[2]; v1.w = col[3];
            v2.x = col[4]; v2.y = col[5]; v2.z = col[6]; v2.w = col[7];
            __stcs((float4*)(g_inner + base), v1);
            __stcs((float4*)(g_inner + base + 4), v2);
        }
    }
}

// ---------------- kernel 3: stats + loss over 2-row slabs (4 CTAs/SM) --------
__global__ void __launch_bounds__(NTHR, 4) stats_loss_kernel() {
    extern __shared__ unsigned char sm[];
    float* rows          = (float*)(sm + SM_ROWS);
    unsigned char* simm  = (unsigned char*)(sm + SM_SIMM);   // 2 bits/j, 4 j/byte
    int*   hist          = (int*)(sm + SM_HIST);
    float* vhist         = (float*)(sm + SM_VHIST);
    float* simv          = (float*)(sm + SM_SIMV);           // alias of vhist
    int*   scnt          = (int*)(sm + SM_SCNT);
    float* sumS2         = (float*)(sm + MISC_SUMS);
    float* sgt2          = (float*)(sm + MISC_SGT);
    float* vsuf2         = (float*)(sm + MISC_VSUF);
    float* sMin2         = (float*)(sm + MISC_SMIN);
    float* BP2           = (float*)(sm + MISC_BP);
    float* BPd2          = (float*)(sm + MISC_BPD);
    float* lp2           = (float*)(sm + MISC_LP);
    float* ln2           = (float*)(sm + MISC_LN);
    int*   nsim2         = (int*)(sm + MISC_NSIM);
    int*   ksel2         = (int*)(sm + MISC_KSEL);
    int*   kk2           = (int*)(sm + MISC_KK);
    unsigned* pfx2       = (unsigned*)(sm + MISC_PFX);
    int*   ep2           = (int*)(sm + MISC_EP);
    int*   en2           = (int*)(sm + MISC_EN);
    float* wscrF         = (float*)(sm + SM_WSCR);
    int*   wscrI         = (int*)(sm + SM_WSCR);

    const int tid = threadIdx.x;
    const int lane = tid & 31, wid = tid >> 5;
    const int i0  = blockIdx.x * RPB;

    // ---- async slab load (48 KB), overlapped with mask build ----
    {
        const unsigned rbase = s2u(rows);
        const float* src = g_inner + (size_t)i0 * NROWS;
        #pragma unroll
        for (int i = 0; i < 6; i++) {
            int idx = tid + i * NTHR;
            cpasync16(rbase + (unsigned)idx * 16u, src + (size_t)idx * 4);
        }
        asm volatile("cp.async.commit_group;" ::: "memory");
    }
    const int lab0 = g_label[i0], lab1 = g_label[i0 + 1];
    for (int b = tid; b < NROWS / 4; b += NTHR) {
        unsigned m = 0;
        #pragma unroll
        for (int jl = 0; jl < 4; jl++) {
            int l = g_label[4 * b + jl];
            m |= (l == lab0) ? (1u << (jl * 2)) : 0u;
            m |= (l == lab1) ? (1u << (jl * 2 + 1)) : 0u;
        }
        simm[b] = (unsigned char)m;
    }
    for (int t = tid; t < RPB * 256; t += NTHR) hist[t] = 0;
    if (tid < RPB) scnt[tid] = 0;
    asm volatile("cp.async.wait_group 0;" ::: "memory");
    __syncthreads();

    // ---- pass-0: warps 0-1 collect similars | warps 2-15 build count hist ----
    if (wid < RPB) {
        int r = wid;
        int off = 0;
        for (int it = 0; it < NROWS / 32; it++) {
            int j = it * 32 + lane;
            bool s = (simm[j >> 2] >> ((j & 3) * 2 + r)) & 1u;
            unsigned bal = __ballot_sync(0xFFFFFFFFu, s);
            if (s) {
                int pos = off + __popc(bal & ((1u << lane) - 1u));
                if (pos < SIMCAP) simv[r * SIMCAP + pos] = rows[r * NROWS + j];
            }
            off += __popc(bal);
        }
        if (lane == 0) scnt[r] = off;
    } else {
        int w = wid - 2;              // 0..13
        int r = w & 1, seg = w >> 1;  // 7 segs x 896 j per row
        int base = seg * 896;
        for (int it = 0; it < 28; it++) {
            int j = base + it * 32 + lane;
            if (j < NROWS) {
                bool dis = !((simm[j >> 2] >> ((j & 3) * 2 + r)) & 1u);
                float v = rows[r * NROWS + j];
                if (dis) aggHistAdd(hist, r * 256 + (int)(f2key(v) >> 24));
            }
        }
    }
    __syncthreads();

    // ---- sumS + sMin + radix init (threads 0..1) ----
    if (tid < RPB) {
        int r = tid;
        int ns = scnt[r];
        nsim2[r] = ns;
        int nd = NROWS - ns;
        int ks = nd - (nd * 9) / 10;
        if (ks < 1) ks = 1;
        ksel2[r] = ks;
        kk2[r]   = ks;
        int cnt = ns < SIMCAP ? ns : SIMCAP;
        float* sv = simv + r * SIMCAP;
        float sS = 0.f;
        for (int i = 0; i < cnt; i++) sS += sv[i];
        sumS2[r] = sS;
        int m = ns - (ns * 9) / 10;
        if (m < 1) m = 1;
        float ssum = 0.f;
        for (int it = 0; it < m && it < cnt; it++) {
            int bi = it; float bv = sv[it];
            for (int t2 = it + 1; t2 < cnt; t2++) {
                float x = sv[t2];
                if (x < bv) { bv = x; bi = t2; }
            }
            sv[bi] = sv[it]; sv[it] = bv;
            ssum += bv;
        }
        sMin2[r] = clip64(ssum / (float)(m > 1 ? m : 1));
    }
    __syncthreads();

    if (wid < RPB) {
        int kknext;
        int b0 = radixPick(hist + wid * 256, kk2[wid], lane, &kknext);
        if (lane == 0) { pfx2[wid] = (unsigned)b0; kk2[wid] = kknext; }
    }
    __syncthreads();

    for (int t = tid; t < RPB * 256; t += NTHR) { hist[t] = 0; vhist[t] = 0.f; }
    __syncthreads();

    // ---- refine sweep: sum above byte-0 bin, 16-bit hist inside bin ----
    {
        unsigned p0[2];
        p0[0] = pfx2[0]; p0[1] = pfx2[1];
        float sg[2];
        sg[0] = 0.f; sg[1] = 0.f;
        for (int j = tid; j < NROWS; j += NTHR) {
            unsigned m = (simm[j >> 2] >> ((j & 3) * 2)) & 3u;
            const float* rj = rows + j;
            #pragma unroll
            for (int r = 0; r < RPB; r++) {
                if (!((m >> r) & 1u)) {
                    float v = rj[r * NROWS];
                    unsigned key = f2key(v);
                    unsigned hi = key >> 24;
                    sg[r] += (hi > p0[r]) ? v : 0.f;
                    if (hi == p0[r]) {
                        int bin = (int)((key >> 16) & 255u);
                        atomicAdd(&hist[r * 256 + bin], 1);
                        atomicAdd(&vhist[r * 256 + bin], v);
                    }
                }
            }
        }
        blockSum2F(sg, wscrF, sgt2, tid);
    }

    if (wid < RPB) {
        int kknext;
        int b1 = radixPick(hist + wid * 256, kk2[wid], lane, &kknext);
        int topbin = 255 - lane * 8;
        float vp = 0.f;
        #pragma unroll
        for (int b = 0; b < 8; b++) {
            int bin = topbin - b;
            if (bin > b1) vp += vhist[wid * 256 + bin];
        }
        #pragma unroll
        for (int o = 16; o > 0; o >>= 1) vp += __shfl_xor_sync(0xFFFFFFFFu, vp, o);
        if (lane == 0) {
            float bm = vhist[wid * 256 + b1] / (float)hist[wid * 256 + b1];
            vsuf2[wid] = vp + (float)kknext * bm;
        }
    }
    __syncthreads();

    // ---- thresholds BP/BPd ----
    if (tid < RPB) {
        int r = tid;
        int ns = nsim2[r], nd = NROWS - ns;
        int ks = ksel2[r];
        float sumD = g_rowsum[i0 + r] - sumS2[r];
        float dsum = sgt2[r] + vsuf2[r];
        float dMax = clip64(dsum / (float)(ks > 1 ? ks : 1));
        float meanS  = clip64(sumS2[r] / fmaxf((float)ns, 1.f));
        float meanDS = clip64(sumD / fmaxf((float)nd, 1.f));
        float sMin = sMin2[r];
        BP2[r]  = meanS  - (64.f - meanS) / 64.f * fabsf(meanS - dMax);
        BPd2[r] = meanDS + meanDS / 64.f * fabsf(meanDS - sMin);
    }
    __syncthreads();

    // ---- loss sweep ----
    {
        const float C1 = -0.2871949906334119f;  // C_COEF = -ln(99)/16
        const float C2 = 2.f * C1;              // A_COEF * C_COEF (a == 2 exactly)
        float bp[2], bpd[2];
        bp[0] = BP2[0]; bp[1] = BP2[1];
        bpd[0] = BPd2[0]; bpd[1] = BPd2[1];
        float lp[2], ln_[2]; int ep[2], en[2];
        lp[0] = lp[1] = 0.f; ln_[0] = ln_[1] = 0.f;
        ep[0] = ep[1] = 0; en[0] = en[1] = 0;
        for (int j = tid; j < NROWS; j += NTHR) {
            unsigned m = (simm[j >> 2] >> ((j & 3) * 2)) & 3u;
            const float* rj = rows + j;
            #pragma unroll
            for (int r = 0; r < RPB; r++) {
                float v = rj[r * NROWS];
                bool sim = (m >> r) & 1u;
                float th  = sim ? bp[r] : bpd[r];
                float dc  = v - th;
                float cpos = sim ? C1 : -C2;
                float cneg = sim ? C2 : -C1;
                float f = ((dc > 0.f) ? cpos : cneg) * dc;
                float sp = softplus_f(f);
                bool eq = (dc == 0.f);
                if (sim) { if (eq) ep[r]++; else lp[r] += sp; }
                else     { if (eq) en[r]++; else ln_[r] += sp; }
            }
        }
        blockSum2F(lp, wscrF, lp2, tid);
        blockSum2F(ln_, wscrF, ln2, tid);
        blockSum2I(ep, wscrI, ep2, tid);
        blockSum2I(en, wscrI, en2, tid);
    }

    if (tid < RPB) {
        int r = tid;
        int ns = nsim2[r], nd = NROWS - ns;
        int cp = ns - ep2[r];
        int cn = nd - en2[r];
        g_rowpos[i0 + r] = lp2[r] / fmaxf((float)cp, 1.f);
        g_rowneg[i0 + r] = ln2[r] / fmaxf((float)cn, 1.f);
        g_valid[i0 + r]  = (ns > 0 && nd > 0) ? 1 : 0;
    }
}

// ---------------- kernel 4: final scalar -------------------------------------
__global__ void __launch_bounds__(256) final_kernel(float* __restrict__ out) {
    __shared__ float scrF[8];
    __shared__ int scrI[8];
    int tid = threadIdx.x;
    float ps = 0.f, ns = 0.f; int cv = 0;
    for (int i = tid; i < NROWS; i += 256) {
        if (g_valid[i]) { ps += g_rowpos[i]; ns += g_rowneg[i]; cv++; }
    }
    float q = 0.f;
    for (int i = tid; i < QBLKS; i += 256) q += g_qpart[i];
    #pragma unroll
    for (int o = 16; o > 0; o >>= 1) {
        ps += __shfl_xor_sync(0xFFFFFFFFu, ps, o);
        ns += __shfl_xor_sync(0xFFFFFFFFu, ns, o);
        cv += __shfl_xor_sync(0xFFFFFFFFu, cv, o);
        q  += __shfl_xor_sync(0xFFFFFFFFu, q, o);
    }
    if ((tid & 31) == 0) { scrF[tid >> 5] = ps; scrI[tid >> 5] = cv; }
    __syncthreads();
    __shared__ float scrF2[8]; __shared__ float scrF3[8];
    if ((tid & 31) == 0) { scrF2[tid >> 5] = ns; scrF3[tid >> 5] = q; }
    __syncthreads();
    if (tid == 0) {
        float psum = 0.f, nsum = 0.f, qs = 0.f; int cnt = 0;
        for (int w = 0; w < 8; w++) {
            psum += scrF[w]; nsum += scrF2[w]; qs += scrF3[w]; cnt += scrI[w];
        }
        float posL = (cnt > 0) ? psum / fmaxf((float)cnt, 1.f) : 0.f;
        float navL = (cnt > 0) ? nsum / fmaxf((float)cnt, 1.f) : 0.f;
        float ql = 0.1f * qs / (float)(NROWS * KDIM);
        out[0] = posL + navL + ql;
    }
}

extern "C" void kernel_launch(void* const* d_in, const int* in_sizes, int n_in,
                              void* d_out, int out_size) {
    const float* u = (const float*)d_in[0];
    const int*   y = (const int*)d_in[1];
    (void)in_sizes; (void)n_in; (void)out_size;

    cudaFuncSetAttribute(gemm_sym_kernel,
                         cudaFuncAttributeMaxDynamicSharedMemorySize, GSMEM2);
    cudaFuncSetAttribute(stats_loss_kernel,
                         cudaFuncAttributeMaxDynamicSharedMemorySize, SMEM_BYTES);

    tanh_kernel<<<QBLKS, 256>>>(u);
    label_kernel<<<NROWS * 32 / 256, 256>>>(y);
    colsum_kernel<<<KDIM, 256>>>();
    rowsum_kernel<<<NROWS / 128, 128>>>();
    dim3 ggrid(NROWS / GTT, NROWS / GTT);     // (48, 48), upper triangle active
    gemm_sym_kernel<<<ggrid, GTHR2, GSMEM2>>>();
    stats_loss_kernel<<<NBLK, NTHR, SMEM_BYTES>>>();
    final_kernel<<<1, 256>>>((float*)d_out);
}

// round 16
// speedup vs baseline: 1.0464x; 1.0464x over previous
#include <cuda_runtime.h>
#include <math.h>

#define NROWS 6144
#define KDIM  128
#define NCLS  200
#define RPB   2
#define NBLK  (NROWS / RPB)      // 3072
#define NTHR  512
#define NWARP (NTHR / 32)        // 16
#define SIMCAP 128
#define QBLKS 192

// symmetric GEMM tiling (R12 version: full K staged, 1 CTA/SM)
#define GTT 128
#define GTHR2 256
#define GSMEM2 (KDIM * GTT * 8)  // 131072

// ---- stats kernel shared memory layout (byte offsets) ----
#define SM_ROWS   0                      // [2][6144] f32 = 49152
#define SM_SIMM   49152                  // packed 4 j/byte (2 bits/j) = 1536
#define SM_HIST   50688                  // [2][256] int = 2048
#define SM_VHIST  52736                  // [2][256] f32 = 2048 (simv aliased pre-refine)
#define SM_SIMV   SM_VHIST               // [2][128] f32 = 1024 (alias)
#define SM_SCNT   54784                  // 32
#define SM_MISC   54816                  // 384
#define SM_WSCR   55200                  // 128
#define SMEM_BYTES 55328

#define MISC_SUMS  (SM_MISC + 0)
#define MISC_SGT   (SM_MISC + 16)
#define MISC_VSUF  (SM_MISC + 32)
#define MISC_SMIN  (SM_MISC + 48)
#define MISC_BP    (SM_MISC + 64)
#define MISC_BPD   (SM_MISC + 80)
#define MISC_LP    (SM_MISC + 96)
#define MISC_LN    (SM_MISC + 112)
#define MISC_NSIM  (SM_MISC + 128)
#define MISC_KSEL  (SM_MISC + 144)
#define MISC_KK    (SM_MISC + 160)
#define MISC_PFX   (SM_MISC + 176)
#define MISC_EPN   (SM_MISC + 192)

static __device__ float g_uhT[KDIM * NROWS];            // transposed tanh(u): [k][j]
static __device__ float g_inner[(size_t)NROWS * NROWS]; // full inner-product matrix
static __device__ float g_colsum[KDIM];
static __device__ float g_rowsum[NROWS];
static __device__ int   g_label[NROWS];
static __device__ float g_rowpos[NROWS];
static __device__ float g_rowneg[NROWS];
static __device__ int   g_valid[NROWS];
static __device__ float g_qpart[QBLKS];

__device__ __forceinline__ unsigned f2key(float f) {
    unsigned u = __float_as_uint(f);
    return u ^ ((unsigned)(((int)u) >> 31) | 0x80000000u);
}
__device__ __forceinline__ float clip64(float x) { return fminf(fmaxf(x, 0.f), 64.f); }
__device__ __forceinline__ float softplus_f(float x) {
    return fmaxf(x, 0.f) + __logf(1.f + __expf(-fabsf(x)));
}
__device__ __forceinline__ unsigned long long packww(float w) {
    unsigned long long r;
    asm("mov.b64 %0, {%1, %1};" : "=l"(r) : "f"(w));
    return r;
}
__device__ __forceinline__ unsigned s2u(const void* p) {
    unsigned a;
    asm("{ .reg .u64 t; cvta.to.shared.u64 t, %1; cvt.u32.u64 %0, t; }"
        : "=r"(a) : "l"(p));
    return a;
}
__device__ __forceinline__ void cpasync16(unsigned saddr, const void* g) {
    asm volatile("cp.async.cg.shared.global [%0], [%1], 16;" :: "r"(saddr), "l"(g));
}
__device__ __forceinline__ float u64lo(unsigned long long a) {
    return __uint_as_float((unsigned)(a & 0xFFFFFFFFull));
}
__device__ __forceinline__ float u64hi(unsigned long long a) {
    return __uint_as_float((unsigned)(a >> 32));
}
__device__ __forceinline__ void aggHistAdd(int* hist, int idx) {
    unsigned active = __activemask();
    unsigned mask = __match_any_sync(active, idx);
    int leader = __ffs(mask) - 1;
    if ((int)(threadIdx.x & 31) == leader)
        atomicAdd(hist + idx, __popc(mask));
}

// deterministic 2-value block reductions (fixed order)
__device__ __forceinline__ void blockSum2F(float v[2], float* wscr, float* out2, int tid) {
    int lane = tid & 31, wid = tid >> 5;
    #pragma unroll
    for (int r = 0; r < 2; r++) {
        #pragma unroll
        for (int o = 16; o > 0; o >>= 1) v[r] += __shfl_xor_sync(0xFFFFFFFFu, v[r], o);
    }
    if (lane == 0) {
        wscr[wid * 2] = v[0];
        wscr[wid * 2 + 1] = v[1];
    }
    __syncthreads();
    if (tid < 2) {
        float s = 0.f;
        #pragma unroll
        for (int w = 0; w < NWARP; w++) s += wscr[w * 2 + tid];
        out2[tid] = s;
    }
    __syncthreads();
}
__device__ __forceinline__ void blockSum2I(int v[2], int* wscr, int* out2, int tid) {
    int lane = tid & 31, wid = tid >> 5;
    #pragma unroll
    for (int r = 0; r < 2; r++) {
        #pragma unroll
        for (int o = 16; o > 0; o >>= 1) v[r] += __shfl_xor_sync(0xFFFFFFFFu, v[r], o);
    }
    if (lane == 0) {
        wscr[wid * 2] = v[0];
        wscr[wid * 2 + 1] = v[1];
    }
    __syncthreads();
    if (tid < 2) {
        int s = 0;
        #pragma unroll
        for (int w = 0; w < NWARP; w++) s += wscr[w * 2 + tid];
        out2[tid] = s;
    }
    __syncthreads();
}

__device__ __forceinline__ int radixPick(const int* histrow, int kk, int lane,
                                         int* kknext_out) {
    int topbin = 255 - lane * 8;
    int csum = 0;
    #pragma unroll
    for (int b = 0; b < 8; b++) csum += histrow[topbin - b];
    int incl = csum;
    #pragma unroll
    for (int o = 1; o < 32; o <<= 1) {
        int t = __shfl_up_sync(0xFFFFFFFFu, incl, o);
        if (lane >= o) incl += t;
    }
    int excl = incl - csum;
    int hit = (excl < kk && kk <= incl) ? 1 : 0;
    unsigned who = __ballot_sync(0xFFFFFFFFu, hit);
    int src = __ffs(who) - 1;
    int bfound = 0, kknext = 0;
    if (hit) {
        int running = excl;
        #pragma unroll
        for (int b = 0; b < 8; b++) {
            int bin = topbin - b;
            int c = histrow[bin];
            running += c;
            if (running >= kk) { bfound = bin; kknext = kk - (running - c); break; }
        }
    }
    bfound = __shfl_sync(0xFFFFFFFFu, bfound, src);
    kknext = __shfl_sync(0xFFFFFFFFu, kknext, src);
    *kknext_out = kknext;
    return bfound;
}

// ---------------- kernel 0: tanh + quantization partials + transpose ----------
__global__ void __launch_bounds__(256) tanh_kernel(const float* __restrict__ u) {
    __shared__ float tile[32][129];
    __shared__ float scr[8];
    const int tid = threadIdx.x;
    const int i0 = blockIdx.x * 32;
    float q = 0.f;
    for (int idx = tid; idx < 32 * KDIM; idx += 256) {
        int r = idx >> 7, k = idx & 127;
        float x = tanhf(u[(i0 + r) * KDIM + k]);
        tile[r][k] = x;
        float s = (x > 0.f) ? 1.f : ((x < 0.f) ? -1.f : 0.f);
        float d = x - s;
        q += d * d;
    }
    __syncthreads();
    for (int idx = tid; idx < 32 * KDIM; idx += 256) {
        int k = idx >> 5, i = idx & 31;
        g_uhT[k * NROWS + i0 + i] = tile[i][k];
    }
    #pragma unroll
    for (int o = 16; o > 0; o >>= 1) q += __shfl_xor_sync(0xFFFFFFFFu, q, o);
    if ((tid & 31) == 0) scr[tid >> 5] = q;
    __syncthreads();
    if (tid == 0) {
        float s = 0.f;
        for (int w = 0; w < 8; w++) s += scr[w];
        g_qpart[blockIdx.x] = s;
    }
}

// ---------------- kernel 1: one-hot -> label (warp per row) ------------------
__global__ void __launch_bounds__(256) label_kernel(const int* __restrict__ y) {
    int w = (blockIdx.x * blockDim.x + threadIdx.x) >> 5;
    int lane = threadIdx.x & 31;
    if (w < NROWS) {
        const int* yr = y + (size_t)w * NCLS;
        int lab = 0;
        for (int c = lane; c < NCLS; c += 32)
            if (yr[c] != 0) lab = c;
        #pragma unroll
        for (int o = 16; o > 0; o >>= 1)
            lab = max(lab, __shfl_xor_sync(0xFFFFFFFFu, lab, o));
        if (lane == 0) g_label[w] = lab;
    }
}

// ---------------- kernel 1b: colsum ------------------------------------------
__global__ void __launch_bounds__(256) colsum_kernel() {
    __shared__ float scr[8];
    const int k = blockIdx.x;
    const int tid = threadIdx.x;
    const float4* p = (const float4*)(g_uhT + (size_t)k * NROWS);
    float a = 0.f;
    for (int t = tid; t < NROWS / 4; t += 256) {
        float4 v = p[t];
        a += (v.x + v.y) + (v.z + v.w);
    }
    #pragma unroll
    for (int o = 16; o > 0; o >>= 1) a += __shfl_xor_sync(0xFFFFFFFFu, a, o);
    if ((tid & 31) == 0) scr[tid >> 5] = a;
    __syncthreads();
    if (tid == 0) {
        float s = 0.f;
        for (int w = 0; w < 8; w++) s += scr[w];
        g_colsum[k] = s;
    }
}

// ---------------- kernel 1c: rowsum ------------------------------------------
__global__ void __launch_bounds__(128) rowsum_kernel() {
    __shared__ float cs[KDIM];
    const int tid = threadIdx.x;
    if (tid < KDIM) cs[tid] = g_colsum[tid];
    __syncthreads();
    int i = blockIdx.x * 128 + tid;
    float a0 = 0.f, a1 = 0.f, a2 = 0.f, a3 = 0.f;
    #pragma unroll
    for (int k = 0; k < KDIM; k += 4) {
        a0 += g_uhT[(size_t)k * NROWS + i] * cs[k];
        a1 += g_uhT[(size_t)(k + 1) * NROWS + i] * cs[k + 1];
        a2 += g_uhT[(size_t)(k + 2) * NROWS + i] * cs[k + 2];
        a3 += g_uhT[(size_t)(k + 3) * NROWS + i] * cs[k + 3];
    }
    g_rowsum[i] = (a0 + a1) + (a2 + a3);
}

// ---------------- kernel 2: SYMMETRIC GEMM (R12 version) ---------------------
__global__ void __launch_bounds__(GTHR2, 1) gemm_sym_kernel() {
    extern __shared__ unsigned long long apk[];   // [KDIM][GTT] (a,a)-packed
    const int it = blockIdx.x, jt = blockIdx.y;
    if (jt < it) return;
    const int tid = threadIdx.x;
    const int i0 = it * GTT;
    const int j0 = jt * GTT;

    for (int t = tid; t < KDIM * GTT; t += GTHR2) {
        int k = t >> 7, i = t & 127;
        apk[k * GTT + i] = packww(g_uhT[(size_t)k * NROWS + i0 + i]);
    }
    __syncthreads();

    const int tii = (tid >> 4) * 8;
    const int tjj = (tid & 15) * 8;
    const float* Bp = g_uhT + (size_t)j0 + tjj;

    unsigned long long acc[8][4];
    #pragma unroll
    for (int i = 0; i < 8; i++)
        #pragma unroll
        for (int c = 0; c < 4; c++) acc[i][c] = 0ull;

    ulonglong2 b01[2], b23[2];
    b01[0] = *(const ulonglong2*)(Bp);
    b23[0] = *(const ulonglong2*)(Bp + 4);
    b01[1] = *(const ulonglong2*)(Bp + (size_t)NROWS);
    b23[1] = *(const ulonglong2*)(Bp + (size_t)NROWS + 4);

    #pragma unroll 2
    for (int k = 0; k < KDIM; k++) {
        const int p = k & 1;
        ulonglong2 cb01 = b01[p], cb23 = b23[p];
        if (k + 2 < KDIM) {
            b01[p] = *(const ulonglong2*)(Bp + (size_t)(k + 2) * NROWS);
            b23[p] = *(const ulonglong2*)(Bp + (size_t)(k + 2) * NROWS + 4);
        }
        const ulonglong2* ap2 = (const ulonglong2*)(apk + k * GTT + tii);
        ulonglong2 ap[4];
        ap[0] = ap2[0]; ap[1] = ap2[1]; ap[2] = ap2[2]; ap[3] = ap2[3];
        unsigned long long a[8];
        #pragma unroll
        for (int h = 0; h < 4; h++) { a[2 * h] = ap[h].x; a[2 * h + 1] = ap[h].y; }
        #pragma unroll
        for (int i = 0; i < 8; i++) {
            asm("fma.rn.f32x2 %0, %1, %2, %0;" : "+l"(acc[i][0]) : "l"(cb01.x), "l"(a[i]));
            asm("fma.rn.f32x2 %0, %1, %2, %0;" : "+l"(acc[i][1]) : "l"(cb01.y), "l"(a[i]));
            asm("fma.rn.f32x2 %0, %1, %2, %0;" : "+l"(acc[i][2]) : "l"(cb23.x), "l"(a[i]));
            asm("fma.rn.f32x2 %0, %1, %2, %0;" : "+l"(acc[i][3]) : "l"(cb23.y), "l"(a[i]));
        }
    }

    #pragma unroll
    for (int i = 0; i < 8; i++) {
        size_t base = (size_t)(i0 + tii + i) * NROWS + j0 + tjj;
        float4 v1, v2;
        v1.x = u64lo(acc[i][0]); v1.y = u64hi(acc[i][0]);
        v1.z = u64lo(acc[i][1]); v1.w = u64hi(acc[i][1]);
        v2.x = u64lo(acc[i][2]); v2.y = u64hi(acc[i][2]);
        v2.z = u64lo(acc[i][3]); v2.w = u64hi(acc[i][3]);
        __stcs((float4*)(g_inner + base), v1);
        __stcs((float4*)(g_inner + base + 4), v2);
    }

    if (it != jt) {
        #pragma unroll
        for (int c = 0; c < 8; c++) {
            float col[8];
            #pragma unroll
            for (int i = 0; i < 8; i++)
                col[i] = (c & 1) ? u64hi(acc[i][c >> 1]) : u64lo(acc[i][c >> 1]);
            size_t base = (size_t)(j0 + tjj + c) * NROWS + i0 + tii;
            float4 v1, v2;
            v1.x = col[0]; v1.y = col[1]; v1.z = col[2]; v1.w = col[3];
            v2.x = col[4]; v2.y = col[5]; v2.z = col[6]; v2.w = col[7];
            __stcs((float4*)(g_inner + base), v1);
            __stcs((float4*)(g_inner + base + 4), v2);
        }
    }
}

// ---------------- kernel 3: stats + loss, float4-vectorized sweeps -----------
__global__ void __launch_bounds__(NTHR, 4) stats_loss_kernel() {
    extern __shared__ unsigned char sm[];
    float* rows          = (float*)(sm + SM_ROWS);
    unsigned char* simm  = (unsigned char*)(sm + SM_SIMM);   // 2 bits/j, 4 j/byte
    int*   hist          = (int*)(sm + SM_HIST);
    float* vhist         = (float*)(sm + SM_VHIST);
    float* simv          = (float*)(sm + SM_SIMV);           // alias of vhist
    int*   scnt          = (int*)(sm + SM_SCNT);
    float* sumS2         = (float*)(sm + MISC_SUMS);
    float* sgt2          = (float*)(sm + MISC_SGT);
    float* vsuf2         = (float*)(sm + MISC_VSUF);
    float* sMin2         = (float*)(sm + MISC_SMIN);
    float* BP2           = (float*)(sm + MISC_BP);
    float* BPd2          = (float*)(sm + MISC_BPD);
    float* lp2           = (float*)(sm + MISC_LP);
    float* ln2           = (float*)(sm + MISC_LN);
    int*   nsim2         = (int*)(sm + MISC_NSIM);
    int*   ksel2         = (int*)(sm + MISC_KSEL);
    int*   kk2           = (int*)(sm + MISC_KK);
    unsigned* pfx2       = (unsigned*)(sm + MISC_PFX);
    int*   epn2          = (int*)(sm + MISC_EPN);
    float* wscrF         = (float*)(sm + SM_WSCR);
    int*   wscrI         = (int*)(sm + SM_WSCR);

    const int tid = threadIdx.x;
    const int lane = tid & 31, wid = tid >> 5;
    const int i0  = blockIdx.x * RPB;

    // ---- async slab load (48 KB), overlapped with mask build ----
    {
        const unsigned rbase = s2u(rows);
        const float* src = g_inner + (size_t)i0 * NROWS;
        #pragma unroll
        for (int i = 0; i < 6; i++) {
            int idx = tid + i * NTHR;
            cpasync16(rbase + (unsigned)idx * 16u, src + (size_t)idx * 4);
        }
        asm volatile("cp.async.commit_group;" ::: "memory");
    }
    const int lab0 = g_label[i0], lab1 = g_label[i0 + 1];
    for (int b = tid; b < NROWS / 4; b += NTHR) {
        unsigned m = 0;
        #pragma unroll
        for (int jl = 0; jl < 4; jl++) {
            int l = g_label[4 * b + jl];
            m |= (l == lab0) ? (1u << (jl * 2)) : 0u;
            m |= (l == lab1) ? (1u << (jl * 2 + 1)) : 0u;
        }
        simm[b] = (unsigned char)m;
    }
    for (int t = tid; t < RPB * 256; t += NTHR) hist[t] = 0;
    if (tid < RPB) scnt[tid] = 0;
    asm volatile("cp.async.wait_group 0;" ::: "memory");
    __syncthreads();

    // ---- pass-0: warps 0-1 collect similars | warps 2-15 hist (float4) ------
    if (wid < RPB) {
        int r = wid;
        int off = 0;
        for (int it = 0; it < NROWS / 32; it++) {
            int j = it * 32 + lane;
            bool s = (simm[j >> 2] >> ((j & 3) * 2 + r)) & 1u;
            unsigned bal = __ballot_sync(0xFFFFFFFFu, s);
            if (s) {
                int pos = off + __popc(bal & ((1u << lane) - 1u));
                if (pos < SIMCAP) simv[r * SIMCAP + pos] = rows[r * NROWS + j];
            }
            off += __popc(bal);
        }
        if (lane == 0) scnt[r] = off;
    } else {
        int w = wid - 2;              // 0..13
        int r = w & 1, seg = w >> 1;  // 7 segs x 896 j per row
        int base = seg * 896;
        const float4* row4 = (const float4*)(rows + r * NROWS);
        for (int it = 0; it < 7; it++) {
            int j4 = (base >> 2) + it * 32 + lane;    // float4 index
            if (j4 * 4 < NROWS) {
                unsigned m = simm[j4];
                float4 v = row4[j4];
                float ve[4] = {v.x, v.y, v.z, v.w};
                #pragma unroll
                for (int jl = 0; jl < 4; jl++) {
                    if (!((m >> (jl * 2 + r)) & 1u))
                        aggHistAdd(hist, r * 256 + (int)(f2key(ve[jl]) >> 24));
                }
            }
        }
    }
    __syncthreads();

    // ---- sumS + sMin + radix init (threads 0..1) ----
    if (tid < RPB) {
        int r = tid;
        int ns = scnt[r];
        nsim2[r] = ns;
        int nd = NROWS - ns;
        int ks = nd - (nd * 9) / 10;
        if (ks < 1) ks = 1;
        ksel2[r] = ks;
        kk2[r]   = ks;
        int cnt = ns < SIMCAP ? ns : SIMCAP;
        float* sv = simv + r * SIMCAP;
        float sS = 0.f;
        for (int i = 0; i < cnt; i++) sS += sv[i];
        sumS2[r] = sS;
        int m = ns - (ns * 9) / 10;
        if (m < 1) m = 1;
        float ssum = 0.f;
        for (int it = 0; it < m && it < cnt; it++) {
            int bi = it; float bv = sv[it];
            for (int t2 = it + 1; t2 < cnt; t2++) {
                float x = sv[t2];
                if (x < bv) { bv = x; bi = t2; }
            }
            sv[bi] = sv[it]; sv[it] = bv;
            ssum += bv;
        }
        sMin2[r] = clip64(ssum / (float)(m > 1 ? m : 1));
    }
    __syncthreads();

    if (wid < RPB) {
        int kknext;
        int b0 = radixPick(hist + wid * 256, kk2[wid], lane, &kknext);
        if (lane == 0) { pfx2[wid] = (unsigned)b0; kk2[wid] = kknext; }
    }
    __syncthreads();

    for (int t = tid; t < RPB * 256; t += NTHR) { hist[t] = 0; vhist[t] = 0.f; }
    __syncthreads();

    // ---- refine sweep (float4): sum above byte-0 bin, 16-bit hist inside ----
    {
        unsigned p0[2];
        p0[0] = pfx2[0]; p0[1] = pfx2[1];
        float sg[2];
        sg[0] = 0.f; sg[1] = 0.f;
        const float4* r04 = (const float4*)(rows);
        const float4* r14 = (const float4*)(rows + NROWS);
        for (int b = tid; b < NROWS / 4; b += NTHR) {
            unsigned m = simm[b];
            float4 v0 = r04[b], v1 = r14[b];
            float ve[2][4] = {{v0.x, v0.y, v0.z, v0.w}, {v1.x, v1.y, v1.z, v1.w}};
            #pragma unroll
            for (int jl = 0; jl < 4; jl++) {
                #pragma unroll
                for (int r = 0; r < RPB; r++) {
                    if (!((m >> (jl * 2 + r)) & 1u)) {
                        float v = ve[r][jl];
                        unsigned key = f2key(v);
                        unsigned hi = key >> 24;
                        sg[r] += (hi > p0[r]) ? v : 0.f;
                        if (hi == p0[r]) {
                            int bin = (int)((key >> 16) & 255u);
                            atomicAdd(&hist[r * 256 + bin], 1);
                            atomicAdd(&vhist[r * 256 + bin], v);
                        }
                    }
                }
            }
        }
        blockSum2F(sg, wscrF, sgt2, tid);
    }

    if (wid < RPB) {
        int kknext;
        int b1 = radixPick(hist + wid * 256, kk2[wid], lane, &kknext);
        int topbin = 255 - lane * 8;
        float vp = 0.f;
        #pragma unroll
        for (int b = 0; b < 8; b++) {
            int bin = topbin - b;
            if (bin > b1) vp += vhist[wid * 256 + bin];
        }
        #pragma unroll
        for (int o = 16; o > 0; o >>= 1) vp += __shfl_xor_sync(0xFFFFFFFFu, vp, o);
        if (lane == 0) {
            float bm = vhist[wid * 256 + b1] / (float)hist[wid * 256 + b1];
            vsuf2[wid] = vp + (float)kknext * bm;
        }
    }
    __syncthreads();

    // ---- thresholds BP/BPd ----
    if (tid < RPB) {
        int r = tid;
        int ns = nsim2[r], nd = NROWS - ns;
        int ks = ksel2[r];
        float sumD = g_rowsum[i0 + r] - sumS2[r];
        float dsum = sgt2[r] + vsuf2[r];
        float dMax = clip64(dsum / (float)(ks > 1 ? ks : 1));
        float meanS  = clip64(sumS2[r] / fmaxf((float)ns, 1.f));
        float meanDS = clip64(sumD / fmaxf((float)nd, 1.f));
        float sMin = sMin2[r];
        BP2[r]  = meanS  - (64.f - meanS) / 64.f * fabsf(meanS - dMax);
        BPd2[r] = meanDS + meanDS / 64.f * fabsf(meanDS - sMin);
    }
    __syncthreads();

    // ---- loss sweep (float4) ----
    {
        const float C1 = -0.2871949906334119f;  // C_COEF = -ln(99)/16
        const float C2 = 2.f * C1;              // A_COEF * C_COEF (a == 2 exactly)
        float bp[2], bpd[2];
        bp[0] = BP2[0]; bp[1] = BP2[1];
        bpd[0] = BPd2[0]; bpd[1] = BPd2[1];
        float lp[2], ln_[2]; int en[2];
        lp[0] = lp[1] = 0.f; ln_[0] = ln_[1] = 0.f;
        en[0] = en[1] = 0;                      // packed: ep | (en<<16)
        const float4* r04 = (const float4*)(rows);
        const float4* r14 = (const float4*)(rows + NROWS);
        for (int b = tid; b < NROWS / 4; b += NTHR) {
            unsigned m = simm[b];
            float4 v0 = r04[b], v1 = r14[b];
            float ve[2][4] = {{v0.x, v0.y, v0.z, v0.w}, {v1.x, v1.y, v1.z, v1.w}};
            #pragma unroll
            for (int jl = 0; jl < 4; jl++) {
                #pragma unroll
                for (int r = 0; r < RPB; r++) {
                    float v = ve[r][jl];
                    bool sim = (m >> (jl * 2 + r)) & 1u;
                    float th  = sim ? bp[r] : bpd[r];
                    float dc  = v - th;
                    float cpos = sim ? C1 : -C2;
                    float cneg = sim ? C2 : -C1;
                    float f = ((dc > 0.f) ? cpos : cneg) * dc;
                    float sp = softplus_f(f);
                    bool eq = (dc == 0.f);
                    if (sim) { if (eq) en[r] += 1; else lp[r] += sp; }
                    else     { if (eq) en[r] += 1 << 16; else ln_[r] += sp; }
                }
            }
        }
        blockSum2F(lp, wscrF, lp2, tid);
        blockSum2F(ln_, wscrF, ln2, tid);
        blockSum2I(en, wscrI, epn2, tid);
    }

    if (tid < RPB) {
        int r = tid;
        int ns = nsim2[r], nd = NROWS - ns;
        int cp = ns - (epn2[r] & 0xFFFF);
        int cn = nd - (epn2[r] >> 16);
        g_rowpos[i0 + r] = lp2[r] / fmaxf((float)cp, 1.f);
        g_rowneg[i0 + r] = ln2[r] / fmaxf((float)cn, 1.f);
        g_valid[i0 + r]  = (ns > 0 && nd > 0) ? 1 : 0;
    }
}

// ---------------- kernel 4: final scalar -------------------------------------
__global__ void __launch_bounds__(256) final_kernel(float* __restrict__ out) {
    __shared__ float scrF[8];
    __shared__ int scrI[8];
    int tid = threadIdx.x;
    float ps = 0.f, ns = 0.f; int cv = 0;
    for (int i = tid; i < NROWS; i += 256) {
        if (g_valid[i]) { ps += g_rowpos[i]; ns += g_rowneg[i]; cv++; }
    }
    float q = 0.f;
    for (int i = tid; i < QBLKS; i += 256) q += g_qpart[i];
    #pragma unroll
    for (int o = 16; o > 0; o >>= 1) {
        ps += __shfl_xor_sync(0xFFFFFFFFu, ps, o);
        ns += __shfl_xor_sync(0xFFFFFFFFu, ns, o);
        cv += __shfl_xor_sync(0xFFFFFFFFu, cv, o);
        q  += __shfl_xor_sync(0xFFFFFFFFu, q, o);
    }
    if ((tid & 31) == 0) { scrF[tid >> 5] = ps; scrI[tid >> 5] = cv; }
    __syncthreads();
    __shared__ float scrF2[8]; __shared__ float scrF3[8];
    if ((tid & 31) == 0) { scrF2[tid >> 5] = ns; scrF3[tid >> 5] = q; }
    __syncthreads();
    if (tid == 0) {
        float psum = 0.f, nsum = 0.f, qs = 0.f; int cnt = 0;
        for (int w = 0; w < 8; w++) {
            psum += scrF[w]; nsum += scrF2[w]; qs += scrF3[w]; cnt += scrI[w];
        }
        float posL = (cnt > 0) ? psum / fmaxf((float)cnt, 1.f) : 0.f;
        float navL = (cnt > 0) ? nsum / fmaxf((float)cnt, 1.f) : 0.f;
        float ql = 0.1f * qs / (float)(NROWS * KDIM);
        out[0] = posL + navL + ql;
    }
}

extern "C" void kernel_launch(void* const* d_in, const int* in_sizes, int n_in,
                              void* d_out, int out_size) {
    const float* u = (const float*)d_in[0];
    const int*   y = (const int*)d_in[1];
    (void)in_sizes; (void)n_in; (void)out_size;

    cudaFuncSetAttribute(gemm_sym_kernel,
                         cudaFuncAttributeMaxDynamicSharedMemorySize, GSMEM2);
    cudaFuncSetAttribute(stats_loss_kernel,
                         cudaFuncAttributeMaxDynamicSharedMemorySize, SMEM_BYTES);

    tanh_kernel<<<QBLKS, 256>>>(u);
    label_kernel<<<NROWS * 32 / 256, 256>>>(y);
    colsum_kernel<<<KDIM, 256>>>();
    rowsum_kernel<<<NROWS / 128, 128>>>();
    dim3 ggrid(NROWS / GTT, NROWS / GTT);     // (48, 48), upper triangle active
    gemm_sym_kernel<<<ggrid, GTHR2, GSMEM2>>>();
    stats_loss_kernel<<<NBLK, NTHR, SMEM_BYTES>>>();
    final_kernel<<<1, 256>>>((float*)d_out);
}